// round 13
// baseline (speedup 1.0000x reference)
#include <cuda_runtime.h>
#include <cuda_bf16.h>
#include <cstdint>

// image_output: [8, 512, 512, 32] f32; slic: [8,512,512,1] i32 in [0,256]
// out[s][b][c] = sum(img where slic-1==s) / count(nonzero img where slic-1==s)

#define BATCH 8
#define HW (512 * 512)
#define CH 32
#define NSEG 256
#define DROW NSEG
#define ROWS (NSEG + 1)

#define CW 3                                // consumer warps per block
#define NTHREADS 128                        // 3 consumers + 1 prefetcher
#define BPB 37                              // 8*37 = 296 blocks = one wave @2/SM
#define GRID_ACC (BATCH * BPB)
#define CHUNK ((HW + BPB - 1) / BPB)        // 7086
#define PF_LEAD 24                          // prefetch lead in 48-px rounds

#define ACCF (ROWS * CH)                    // 8224 floats per consumer-warp acc
#define SMEM_BYTES (CW * ACCF * 4)          // 98688 -> 2 blocks/SM

#define PREP_BLOCKS 1024
#define PIX_PER_PREP (BATCH * HW / PREP_BLOCKS)   // 2048
#define CNT_BLK_PER_BATCH (PREP_BLOCKS / BATCH)   // 128

__device__ float g_part[GRID_ACC][NSEG * CH];     // per-block sum partials
__device__ float g_cntp[PREP_BLOCKS][NSEG];       // per-prep-block pixel counts
__device__ float g_zc[BATCH][NSEG][CH];           // exact-zero corrections.
// INVARIANT: g_zc == 0 at every kernel_launch entry (finalize re-zeros).

// ---------------------------------------------------------------------------
// 16-pixel smem RMW. Fast path (no dup within distance<=3, ~84%): repair-free
// pipelined LDS->FADD->STS with prefetch-3. Slow path: exact depth-2 repair.
// ---------------------------------------------------------------------------
__device__ __forceinline__ void process16(
    const float v[16], int mysv, float* __restrict__ acc, int lane, bool& zacc)
{
    const unsigned FULL = 0xffffffffu;
    int myrow = (mysv == 0) ? DROW : (mysv - 1);

    int d1 = __shfl_up_sync(FULL, myrow, 1);
    int d2 = __shfl_up_sync(FULL, myrow, 2);
    int d3 = __shfl_up_sync(FULL, myrow, 3);
    bool bad = (lane < 16) && (((lane >= 1) && (myrow == d1)) ||
                               ((lane >= 2) && (myrow == d2)) ||
                               ((lane >= 3) && (myrow == d3)));
    unsigned badm = __ballot_sync(FULL, bad);

    int row[16];
    #pragma unroll
    for (int u = 0; u < 16; ++u) row[u] = __shfl_sync(FULL, myrow, u);

    // Exact-zero detect via min-|v| tree (FMNMX; |.| is a free modifier).
    float mn = fabsf(v[0]);
    #pragma unroll
    for (int u = 1; u < 16; ++u) mn = fminf(mn, fabsf(v[u]));
    zacc |= (mn == 0.0f);

    if (badm == 0) {
        // FAST: rows pairwise distinct within distance 3 -> no aliasing with
        // prefetch-3, no serial dependency across iterations.
        float p0 = acc[row[0] * CH + lane];
        float p1 = acc[row[1] * CH + lane];
        float p2 = acc[row[2] * CH + lane];
        #pragma unroll
        for (int u = 0; u < 16; ++u) {
            float a = p0 + v[u];
            float np = 0.0f;
            if (u + 3 < 16) np = acc[row[u + 3] * CH + lane];
            acc[row[u] * CH + lane] = a;
            p0 = p1; p1 = p2; p2 = np;
        }
    } else {
        // SLOW: exact depth-2 repair (handles any duplicate pattern).
        float p0 = acc[row[0] * CH + lane];
        float p1 = acc[row[1] * CH + lane];
        int   lr = -1, l2r = -1;
        float lv = 0.f, l2v = 0.f;
        #pragma unroll
        for (int u = 0; u < 16; ++u) {
            float a = p0;
            a = (row[u] == l2r) ? l2v : a;
            a = (row[u] == lr)  ? lv  : a;
            a += v[u];
            float np = 0.0f;
            if (u + 2 < 16) np = acc[row[u + 2] * CH + lane];
            acc[row[u] * CH + lane] = a;
            l2r = lr;  l2v = lv;
            lr = row[u]; lv = a;
            p0 = p1; p1 = np;
        }
    }
}

// ---------------------------------------------------------------------------
// L2 prefetch of one 48-px block round (6 KB img + 192 B slic). No dest reg,
// no scoreboard entry -> unbounded outstanding DRAM requests.
// ---------------------------------------------------------------------------
__device__ __forceinline__ void prefetch_round(
    const float* imgb, const int* slicb, int pb, int lane)
{
    const char* a0 = (const char*)(imgb + (size_t)pb * CH) + lane * 128;
    const char* a1 = (const char*)(imgb + (size_t)(pb + 32) * CH) + (lane & 15) * 128;
    const char* s0 = (const char*)(slicb + pb) + (lane & 3) * 63;
    asm volatile("prefetch.global.L2 [%0];" :: "l"(a0));
    asm volatile("prefetch.global.L2 [%0];" :: "l"(a1));
    asm volatile("prefetch.global.L2 [%0];" :: "l"(s0));
}

// ---------------------------------------------------------------------------
// Kernel A: segmented accumulation. 3 consumer warps (SMSPs 0-2) + 1 prefetch
// warp (SMSP 3) per block, 2 blocks/SM. Depth-6 register ring on consumers;
// prefetcher keeps the stream in L2 ~24 rounds ahead (paced via smem counter).
// ---------------------------------------------------------------------------
#define LOAD_ROUND(BUF, SV, k) do {                                          \
    int pb_ = start + (int)(k) * (CW * 16) + warp * 16;                      \
    pb_ = (pb_ > end - 16) ? (end - 16) : pb_;   /* clamp: always in range */\
    const float* ibp_ = imgb + (size_t)pb_ * CH + lane;                      \
    _Pragma("unroll")                                                        \
    for (int u_ = 0; u_ < 16; ++u_) BUF[u_] = __ldcs(ibp_ + u_ * CH);        \
    SV = slicb[pb_ + (lane & 15)];                                           \
} while (0)

__global__ void __launch_bounds__(NTHREADS, 2)
accum_kernel(const float* __restrict__ img, const int* __restrict__ slic) {
    extern __shared__ float smem[];
    __shared__ int zflag[4];
    __shared__ volatile int prog;
    const int tid  = threadIdx.x;
    const int warp = tid >> 5;
    const int lane = tid & 31;
    if (tid == 0) prog = 0;
    if (lane == 0) zflag[warp] = 0;

    for (int i = tid; i < CW * ACCF / 4; i += NTHREADS)
        ((float4*)smem)[i] = make_float4(0.f, 0.f, 0.f, 0.f);
    __syncthreads();

    const int batch = blockIdx.x / BPB;
    const int blk   = blockIdx.x % BPB;
    const float* imgb  = img  + (size_t)batch * HW * CH;
    const int*   slicb = slic + (size_t)batch * HW;

    const int start = blk * CHUNK;
    int end = start + CHUNK; if (end > HW) end = HW;
    const int n = end - start;
    const int nfull = n / (CW * 16);            // 48-px block rounds (~147)

    const unsigned FULL = 0xffffffffu;

    if (warp == 3) {
        // ---- Prefetch warp (SMSP 3): stream img+slic into L2, paced. ----
        int k = 0;
        while (k < nfull) {
            int lim = prog + PF_LEAD;
            if (lim > nfull) lim = nfull;
            if (k < lim) {
                prefetch_round(imgb, slicb, start + k * (CW * 16), lane);
                ++k;
            } else {
                __nanosleep(256);
            }
        }
    } else {
        // ---- Consumer warps 0-2 (SMSPs 0-2): depth-6 register ring. ----
        float* acc = smem + warp * ACCF;
        bool zacc = false;

        float B0[16], B1[16], B2[16], B3[16], B4[16], B5[16];
        int   S0, S1, S2, S3, S4, S5;
        LOAD_ROUND(B0, S0, 0);
        LOAD_ROUND(B1, S1, 1);
        LOAD_ROUND(B2, S2, 2);
        LOAD_ROUND(B3, S3, 3);
        LOAD_ROUND(B4, S4, 4);

        int r = 0;
        for (; r + 6 <= nfull; r += 6) {
            if (warp == 0) prog = r;            // pace the prefetcher
            LOAD_ROUND(B5, S5, r + 5);  process16(B0, S0, acc, lane, zacc);
            LOAD_ROUND(B0, S0, r + 6);  process16(B1, S1, acc, lane, zacc);
            LOAD_ROUND(B1, S1, r + 7);  process16(B2, S2, acc, lane, zacc);
            LOAD_ROUND(B2, S2, r + 8);  process16(B3, S3, acc, lane, zacc);
            LOAD_ROUND(B3, S3, r + 9);  process16(B4, S4, acc, lane, zacc);
            LOAD_ROUND(B4, S4, r + 10); process16(B5, S5, acc, lane, zacc);
        }
        const int rem = nfull - r;
        if (rem > 0) process16(B0, S0, acc, lane, zacc);
        if (rem > 1) process16(B1, S1, acc, lane, zacc);
        if (rem > 2) process16(B2, S2, acc, lane, zacc);
        if (rem > 3) process16(B3, S3, acc, lane, zacc);
        if (rem > 4) process16(B4, S4, acc, lane, zacc);

        if (warp == 0) prog = nfull + PF_LEAD;  // release prefetcher (no deadlock)

        // Tail: < 48 leftover pixels, one pixel per consumer warp per step.
        for (int p = start + nfull * (CW * 16) + warp; p < end; p += CW) {
            int s = slicb[p];
            int rw = (s == 0) ? DROW : (s - 1);
            float x = imgb[(size_t)p * CH + lane];
            acc[rw * CH + lane] += x;
            zacc |= (x == 0.0f);
        }

        if (__ballot_sync(FULL, zacc) && lane == 0) zflag[warp] = 1;
    }

    // Merge 3 consumer accumulators; stream 256 real sum rows to global.
    __syncthreads();
    float4* outp = (float4*)g_part[blockIdx.x];
    #pragma unroll 4
    for (int i = tid; i < NSEG * CH / 4; i += NTHREADS) {
        float4 a = ((const float4*)smem)[i];
        #pragma unroll
        for (int w = 1; w < CW; ++w) {
            float4 b = ((const float4*)(smem + w * ACCF))[i];
            a.x += b.x; a.y += b.y; a.z += b.z; a.w += b.w;
        }
        outp[i] = a;
    }

    // Exact-zero correction path (essentially never taken; exact when it is).
    int anyz = zflag[0] | zflag[1] | zflag[2] | zflag[3];
    if (anyz && warp < CW) {
        for (int p = start + warp; p < end; p += CW) {
            int s = slicb[p];
            if (s == 0) continue;
            float x = imgb[(size_t)p * CH + lane];
            if (x == 0.0f) atomicAdd(&g_zc[batch][s - 1][lane], 1.0f);
        }
    }
}

// ---------------------------------------------------------------------------
// Kernel B: per-segment pixel counts from slic (int4 x2 per thread).
// ---------------------------------------------------------------------------
__global__ void prep_kernel(const int* __restrict__ slic) {
    __shared__ int cnt[NSEG];
    const int t = threadIdx.x;
    cnt[t] = 0;
    __syncthreads();

    const int4* p = (const int4*)(slic + blockIdx.x * PIX_PER_PREP);
    int4 a = p[t];
    int4 b = p[256 + t];
    if (a.x) atomicAdd(&cnt[a.x - 1], 1);
    if (a.y) atomicAdd(&cnt[a.y - 1], 1);
    if (a.z) atomicAdd(&cnt[a.z - 1], 1);
    if (a.w) atomicAdd(&cnt[a.w - 1], 1);
    if (b.x) atomicAdd(&cnt[b.x - 1], 1);
    if (b.y) atomicAdd(&cnt[b.y - 1], 1);
    if (b.z) atomicAdd(&cnt[b.z - 1], 1);
    if (b.w) atomicAdd(&cnt[b.w - 1], 1);
    __syncthreads();
    g_cntp[blockIdx.x][t] = (float)cnt[t];
}

// ---------------------------------------------------------------------------
// Kernel C: 4-way k-split reduction + divide. grid 1024 x 256.
// ---------------------------------------------------------------------------
__global__ void finalize_kernel(float* __restrict__ out) {
    __shared__ float ssum[256], scnt[256];
    const int t = threadIdx.x;
    const int slice = t >> 6;                          // 0..3
    const int o = (blockIdx.x << 6) | (t & 63);        // output id 0..65535
    const int c = o & (CH - 1);
    const int s = (o >> 5) & (NSEG - 1);
    const int b = o >> 13;

    float sum = 0.0f;
    {
        int k0 = (slice * BPB) >> 2, k1 = ((slice + 1) * BPB) >> 2;
        int pb = b * BPB;
        for (int k = k0; k < k1; ++k)
            sum += g_part[pb + k][s * CH + c];         // coalesced over c
    }
    float cn = 0.0f;
    {
        int k0 = slice * 32, k1 = k0 + 32;
        int cb = b * CNT_BLK_PER_BATCH;
        #pragma unroll 8
        for (int k = k0; k < k1; ++k)
            cn += g_cntp[cb + k][s];                   // warp-broadcast
    }
    ssum[t] = sum; scnt[t] = cn;
    __syncthreads();

    if (t < 64) {
        sum = ssum[t] + ssum[t + 64] + ssum[t + 128] + ssum[t + 192];
        cn  = scnt[t] + scnt[t + 64] + scnt[t + 128] + scnt[t + 192];
        cn -= g_zc[b][s][c];
        g_zc[b][s][c] = 0.0f;                          // restore invariant
        out[((size_t)s * BATCH + b) * CH + c] = sum / cn;
    }
}

// ---------------------------------------------------------------------------
extern "C" void kernel_launch(void* const* d_in, const int* in_sizes, int n_in,
                              void* d_out, int out_size) {
    const float* img  = (const float*)d_in[0];
    const int*   slic = (const int*)d_in[1];
    float* out = (float*)d_out;

    // accum first so ncu's bounded capture profiles the hot kernel.
    cudaFuncSetAttribute(accum_kernel,
                         cudaFuncAttributeMaxDynamicSharedMemorySize, SMEM_BYTES);
    accum_kernel<<<GRID_ACC, NTHREADS, SMEM_BYTES>>>(img, slic);

    prep_kernel<<<PREP_BLOCKS, 256>>>(slic);

    finalize_kernel<<<1024, 256>>>(out);
}

// round 14
// speedup vs baseline: 1.5574x; 1.5574x over previous
#include <cuda_runtime.h>
#include <cuda_bf16.h>
#include <cstdint>

// image_output: [8, 512, 512, 32] f32; slic: [8,512,512,1] i32 in [0,256]
// out[s][b][c] = sum(img where slic-1==s) / count(nonzero img where slic-1==s)

#define BATCH 8
#define HW (512 * 512)
#define CH 32
#define NSEG 256
#define DROW NSEG
#define ROWS (NSEG + 1)

#define WPB 3                               // 3 warps/block, 2 blocks/SM
#define BPB 37                              // 296 blocks = one wave @2/SM
#define GRID_ACC (BATCH * BPB)
#define CHUNK ((HW + BPB - 1) / BPB)        // 7086
#define RPX (WPB * 32)                      // 96 px per block round

#define ACCF (ROWS * CH)                    // 8224 floats per warp accumulator
#define SMEM_BYTES (WPB * ACCF * 4)         // 98688 -> 2 blocks/SM

#define PREP_BLOCKS 1024
#define PIX_PER_PREP (BATCH * HW / PREP_BLOCKS)   // 2048
#define CNT_BLK_PER_BATCH (PREP_BLOCKS / BATCH)   // 128

__device__ float g_part[GRID_ACC][NSEG * CH];     // per-block sum partials
__device__ float g_cntp[PREP_BLOCKS][NSEG];       // per-prep-block pixel counts
__device__ float g_zc[BATCH][NSEG][CH];           // exact-zero corrections.
// INVARIANT: g_zc == 0 at every kernel_launch entry (finalize re-zeros).

// ---------------------------------------------------------------------------
// One round = 16 steps x 2 px = 32 px. Lane (h,q) handles channels (2q,2q+1)
// of pixel 2u+h via float2. Word (row, 2q) is written by lanes (0,q),(1,q),
// so the fast path requires no duplicate rows at pixel distance 1..7
// (distance 1 covers the same-step pair -> no dedup needed on fast path).
// ---------------------------------------------------------------------------
__device__ __forceinline__ void process32(
    const float2 v[16], int rowv, float* __restrict__ acc,
    int lane, int h, int q, bool& zacc)
{
    const unsigned FULL = 0xffffffffu;

    // Hazard guard: any equal rows at pixel distance 1..7 in this round?
    bool bad = false;
    #pragma unroll
    for (int d = 1; d <= 7; ++d) {
        int rd = __shfl_up_sync(FULL, rowv, d);
        bad |= (lane >= d) && (rowv == rd);
    }
    unsigned badm = __ballot_sync(FULL, bad);

    // Exact-zero detect via min-|v| tree.
    float mn = fminf(fabsf(v[0].x), fabsf(v[0].y));
    #pragma unroll
    for (int u = 1; u < 16; ++u)
        mn = fminf(mn, fminf(fabsf(v[u].x), fabsf(v[u].y)));
    zacc |= (mn == 0.0f);

    if (badm == 0) {
        // FAST (~47%): all rows distinct within distance 7 -> no same-step
        // dup, no aliasing with prefetch-3, no serial dependency.
        int er[16];
        #pragma unroll
        for (int u = 0; u < 16; ++u) er[u] = __shfl_sync(FULL, rowv, 2 * u + h);
        float2 p0 = *(float2*)(acc + er[0] * CH + 2 * q);
        float2 p1 = *(float2*)(acc + er[1] * CH + 2 * q);
        float2 p2 = *(float2*)(acc + er[2] * CH + 2 * q);
        #pragma unroll
        for (int u = 0; u < 16; ++u) {
            float2 a; a.x = p0.x + v[u].x; a.y = p0.y + v[u].y;
            float2 np = make_float2(0.f, 0.f);
            if (u + 3 < 16) np = *(float2*)(acc + er[u + 3] * CH + 2 * q);
            *(float2*)(acc + er[u] * CH + 2 * q) = a;
            p0 = p1; p1 = p2; p2 = np;
        }
    } else {
        // SLOW: per-step intra-pair dedup (absorber h==0 takes both values,
        // h==1 redirects to dummy row), then strictly serial float2 RMW --
        // exact by warp program order across steps.
        int dup = (rowv == __shfl_xor_sync(FULL, rowv, 1)) ? 1 : 0;
        int pk  = (rowv << 1) | dup;
        #pragma unroll
        for (int u = 0; u < 16; ++u) {
            int   m  = __shfl_sync(FULL, pk, 2 * u + h);
            float px = __shfl_xor_sync(FULL, v[u].x, 16);
            float py = __shfl_xor_sync(FULL, v[u].y, 16);
            int   er = m >> 1;
            bool  d  = (m & 1) != 0;
            float ax = v[u].x + ((d && h == 0) ? px : 0.0f);
            float ay = v[u].y + ((d && h == 0) ? py : 0.0f);
            int   e  = (d && h == 1) ? DROW : er;
            float2* w = (float2*)(acc + e * CH + 2 * q);
            float2 cur = *w;
            cur.x += ax; cur.y += ay;
            *w = cur;
        }
    }
}

// ---------------------------------------------------------------------------
// Kernel A: segmented accumulation. 3 warps/block, 2 blocks/SM. LDG.64
// (float2) loads: 55-deep per-warp LDG window now holds 14 KB -> 84 KB
// in-flight per SM. Depth-4 register ring (lead 3 rounds = 51 LDG slots).
// ---------------------------------------------------------------------------
#define LOAD_ROUND(BUF, RV, k) do {                                          \
    int pb_ = start + (int)(k) * RPX + warp * 32;                            \
    pb_ = (pb_ > end - 32) ? (end - 32) : pb_;   /* clamp: always in range */\
    const float2* ip_ = (const float2*)imgb + (size_t)(pb_ + h) * 16 + q;    \
    _Pragma("unroll")                                                        \
    for (int u_ = 0; u_ < 16; ++u_) BUF[u_] = __ldcs(ip_ + u_ * 32);         \
    int sv_ = slicb[pb_ + lane];                                             \
    RV = (sv_ == 0) ? DROW : (sv_ - 1);                                      \
} while (0)

__global__ void __launch_bounds__(WPB * 32, 2)
accum_kernel(const float* __restrict__ img, const int* __restrict__ slic) {
    extern __shared__ float smem[];
    __shared__ int zflag[WPB];
    const int tid  = threadIdx.x;
    const int warp = tid >> 5;
    const int lane = tid & 31;
    const int h    = lane >> 4;
    const int q    = lane & 15;
    float* acc = smem + warp * ACCF;
    if (lane == 0) zflag[warp] = 0;

    float4* a4 = (float4*)acc;
    for (int i = lane; i < ACCF / 4; i += 32)
        a4[i] = make_float4(0.f, 0.f, 0.f, 0.f);
    __syncwarp();

    const int batch = blockIdx.x / BPB;
    const int blk   = blockIdx.x % BPB;
    const float* imgb  = img  + (size_t)batch * HW * CH;
    const int*   slicb = slic + (size_t)batch * HW;

    const int start = blk * CHUNK;
    int end = start + CHUNK; if (end > HW) end = HW;
    const int n = end - start;
    const int nfull = n / RPX;                  // 96-px block rounds (~73)

    const unsigned FULL = 0xffffffffu;
    bool zacc = false;

    float2 B0[16], B1[16], B2[16], B3[16];
    int    S0, S1, S2, S3;
    LOAD_ROUND(B0, S0, 0);
    LOAD_ROUND(B1, S1, 1);
    LOAD_ROUND(B2, S2, 2);

    int r = 0;
    for (; r + 4 <= nfull; r += 4) {
        LOAD_ROUND(B3, S3, r + 3); process32(B0, S0, acc, lane, h, q, zacc);
        LOAD_ROUND(B0, S0, r + 4); process32(B1, S1, acc, lane, h, q, zacc);
        LOAD_ROUND(B1, S1, r + 5); process32(B2, S2, acc, lane, h, q, zacc);
        LOAD_ROUND(B2, S2, r + 6); process32(B3, S3, acc, lane, h, q, zacc);
    }
    const int rem = nfull - r;
    if (rem > 0) process32(B0, S0, acc, lane, h, q, zacc);
    if (rem > 1) process32(B1, S1, acc, lane, h, q, zacc);
    if (rem > 2) process32(B2, S2, acc, lane, h, q, zacc);

    // Tail: < 96 leftover pixels; one pixel per warp per step, lanes 0-15
    // each own a distinct float2 word -> serial per warp, exact.
    for (int p = start + nfull * RPX + warp; p < end; p += WPB) {
        int s = slicb[p];
        int rw = (s == 0) ? DROW : (s - 1);
        if (h == 0) {
            float2 x = *((const float2*)imgb + (size_t)p * 16 + q);
            float2* w = (float2*)(acc + rw * CH + 2 * q);
            float2 cur = *w;
            cur.x += x.x; cur.y += x.y;
            *w = cur;
            zacc |= (x.x == 0.0f) | (x.y == 0.0f);
        }
    }

    if (__ballot_sync(FULL, zacc) && lane == 0) zflag[warp] = 1;

    // Merge 3 warp accumulators; stream 256 real sum rows to global.
    __syncthreads();
    float4* outp = (float4*)g_part[blockIdx.x];
    #pragma unroll 4
    for (int i = tid; i < NSEG * CH / 4; i += WPB * 32) {
        float4 a = ((const float4*)smem)[i];
        #pragma unroll
        for (int w = 1; w < WPB; ++w) {
            float4 b = ((const float4*)(smem + w * ACCF))[i];
            a.x += b.x; a.y += b.y; a.z += b.z; a.w += b.w;
        }
        outp[i] = a;
    }

    // Exact-zero correction path (essentially never taken; exact when it is).
    int anyz = zflag[0] | zflag[1] | zflag[2];
    if (anyz) {
        for (int p = start + warp; p < end; p += WPB) {
            int s = slicb[p];
            if (s == 0) continue;
            float x = imgb[(size_t)p * CH + lane];
            if (x == 0.0f) atomicAdd(&g_zc[batch][s - 1][lane], 1.0f);
        }
    }
}

// ---------------------------------------------------------------------------
// Kernel B: per-segment pixel counts from slic (int4 x2 per thread).
// ---------------------------------------------------------------------------
__global__ void prep_kernel(const int* __restrict__ slic) {
    __shared__ int cnt[NSEG];
    const int t = threadIdx.x;
    cnt[t] = 0;
    __syncthreads();

    const int4* p = (const int4*)(slic + blockIdx.x * PIX_PER_PREP);
    int4 a = p[t];
    int4 b = p[256 + t];
    if (a.x) atomicAdd(&cnt[a.x - 1], 1);
    if (a.y) atomicAdd(&cnt[a.y - 1], 1);
    if (a.z) atomicAdd(&cnt[a.z - 1], 1);
    if (a.w) atomicAdd(&cnt[a.w - 1], 1);
    if (b.x) atomicAdd(&cnt[b.x - 1], 1);
    if (b.y) atomicAdd(&cnt[b.y - 1], 1);
    if (b.z) atomicAdd(&cnt[b.z - 1], 1);
    if (b.w) atomicAdd(&cnt[b.w - 1], 1);
    __syncthreads();
    g_cntp[blockIdx.x][t] = (float)cnt[t];
}

// ---------------------------------------------------------------------------
// Kernel C: 4-way k-split reduction + divide. grid 1024 x 256.
// ---------------------------------------------------------------------------
__global__ void finalize_kernel(float* __restrict__ out) {
    __shared__ float ssum[256], scnt[256];
    const int t = threadIdx.x;
    const int slice = t >> 6;                          // 0..3
    const int o = (blockIdx.x << 6) | (t & 63);        // output id 0..65535
    const int c = o & (CH - 1);
    const int s = (o >> 5) & (NSEG - 1);
    const int b = o >> 13;

    float sum = 0.0f;
    {
        int k0 = (slice * BPB) >> 2, k1 = ((slice + 1) * BPB) >> 2;
        int pb = b * BPB;
        for (int k = k0; k < k1; ++k)
            sum += g_part[pb + k][s * CH + c];         // coalesced over c
    }
    float cn = 0.0f;
    {
        int k0 = slice * 32, k1 = k0 + 32;
        int cb = b * CNT_BLK_PER_BATCH;
        #pragma unroll 8
        for (int k = k0; k < k1; ++k)
            cn += g_cntp[cb + k][s];                   // warp-broadcast
    }
    ssum[t] = sum; scnt[t] = cn;
    __syncthreads();

    if (t < 64) {
        sum = ssum[t] + ssum[t + 64] + ssum[t + 128] + ssum[t + 192];
        cn  = scnt[t] + scnt[t + 64] + scnt[t + 128] + scnt[t + 192];
        cn -= g_zc[b][s][c];
        g_zc[b][s][c] = 0.0f;                          // restore invariant
        out[((size_t)s * BATCH + b) * CH + c] = sum / cn;
    }
}

// ---------------------------------------------------------------------------
extern "C" void kernel_launch(void* const* d_in, const int* in_sizes, int n_in,
                              void* d_out, int out_size) {
    const float* img  = (const float*)d_in[0];
    const int*   slic = (const int*)d_in[1];
    float* out = (float*)d_out;

    // accum first so ncu's bounded capture profiles the hot kernel.
    cudaFuncSetAttribute(accum_kernel,
                         cudaFuncAttributeMaxDynamicSharedMemorySize, SMEM_BYTES);
    accum_kernel<<<GRID_ACC, WPB * 32, SMEM_BYTES>>>(img, slic);

    prep_kernel<<<PREP_BLOCKS, 256>>>(slic);

    finalize_kernel<<<1024, 256>>>(out);
}